// round 15
// baseline (speedup 1.0000x reference)
#include <cuda_runtime.h>
#include <cuda_bf16.h>
#include <math.h>

#define Nn 100000
#define Ee 1600000
#define Gg 512
#define Hh 128
#define SCAN_CHUNK 1024
#define NBLK_SCAN ((Nn + SCAN_CHUNK - 1) / SCAN_CHUNK)   // 98

#define AP 132                                  // A-chunk row pitch (floats)
#define WP 132                                  // Wt row pitch (floats)
#define SMEM_W_FLOATS (128 * WP)                // W transposed [n][k]
#define SMEM_A_FLOATS (2 * 32 * AP)             // double-buffered 32-row chunks
#define FUSED_SMEM ((SMEM_W_FLOATS + SMEM_A_FLOATS) * 4)   // 101376 bytes

#define BAR_FULL0 1
#define BAR_FULL1 2
#define BAR_FREE0 3
#define BAR_FREE1 4
#define BAR_CONS  5

__device__ __forceinline__ void bar_sync(int id, int cnt) {
    asm volatile("bar.sync %0, %1;" :: "r"(id), "r"(cnt) : "memory");
}
__device__ __forceinline__ void bar_arrive(int id, int cnt) {
    asm volatile("bar.arrive %0, %1;" :: "r"(id), "r"(cnt) : "memory");
}

// fp32 -> (tf32 hi, tf32 lo) split
__device__ __forceinline__ void tf32_split(float a, unsigned& hi, unsigned& lo) {
    asm("cvt.rna.tf32.f32 %0, %1;" : "=r"(hi) : "f"(a));
    float r = a - __uint_as_float(hi);
    asm("cvt.rna.tf32.f32 %0, %1;" : "=r"(lo) : "f"(r));
}

__device__ __forceinline__ void mma_tf32(float* c, const unsigned* a,
                                         unsigned b0, unsigned b1) {
    asm volatile(
        "mma.sync.aligned.m16n8k8.row.col.f32.tf32.tf32.f32 "
        "{%0,%1,%2,%3}, {%4,%5,%6,%7}, {%8,%9}, {%0,%1,%2,%3};"
        : "+f"(c[0]), "+f"(c[1]), "+f"(c[2]), "+f"(c[3])
        : "r"(a[0]), "r"(a[1]), "r"(a[2]), "r"(a[3]), "r"(b0), "r"(b1));
}

// ---------------- scratch (device globals; no allocation allowed) ----------
__device__ float g_h0[(size_t)Nn * Hh];
__device__ float g_h1[(size_t)Nn * Hh];
__device__ float g_norm_out[Nn];
__device__ float g_norm_in[Nn];
__device__ float g_gsum[(size_t)Gg * Hh];

__device__ int g_cnt_in[Nn];
__device__ int g_cnt_out[Nn];
__device__ int g_rowptr[Nn + 1];
__device__ int g_cursor[Nn];
__device__ int g_csrc[Ee];
__device__ int g_partials[256];

// ---------------- zero kernels ---------------------------------------------
__global__ void zero_cnt_kernel() {
    int i = blockIdx.x * blockDim.x + threadIdx.x;
    if (i < Nn) { g_cnt_in[i] = 0; g_cnt_out[i] = 0; }
}

__global__ void zero_g_kernel() {
    int i = blockIdx.x * blockDim.x + threadIdx.x;
    if (i < Gg * Hh) g_gsum[i] = 0.f;
}

// ---------------- histogram (also yields degrees) --------------------------
__global__ void hist_kernel(const int* __restrict__ src, const int* __restrict__ dst) {
    int e = blockIdx.x * blockDim.x + threadIdx.x;
    if (e < Ee) {
        atomicAdd(&g_cnt_in[dst[e]], 1);
        atomicAdd(&g_cnt_out[src[e]], 1);
    }
}

__global__ void norm_kernel() {
    int i = blockIdx.x * blockDim.x + threadIdx.x;
    if (i < Nn) {
        g_norm_out[i] = rsqrtf(fmaxf((float)g_cnt_out[i], 1.f));
        g_norm_in[i]  = rsqrtf(fmaxf((float)g_cnt_in[i], 1.f));
    }
}

// ---------------- 3-phase exclusive scan of g_cnt_in -> g_rowptr -----------
__global__ void scan1_kernel() {
    __shared__ int sm[256];
    int b = blockIdx.x, t = threadIdx.x;
    int base = b * SCAN_CHUNK + t * 4;
    int v[4]; int s = 0;
#pragma unroll
    for (int i = 0; i < 4; i++) {
        int idx = base + i;
        v[i] = (idx < Nn) ? g_cnt_in[idx] : 0;
        s += v[i];
    }
    sm[t] = s;
    __syncthreads();
    for (int off = 1; off < 256; off <<= 1) {
        int x = (t >= off) ? sm[t - off] : 0;
        __syncthreads();
        if (t >= off) sm[t] += x;
        __syncthreads();
    }
    int run = (t > 0) ? sm[t - 1] : 0;
#pragma unroll
    for (int i = 0; i < 4; i++) {
        int idx = base + i;
        if (idx < Nn) g_rowptr[idx] = run;
        run += v[i];
    }
    if (t == 255) g_partials[b] = sm[255];
}

__global__ void scan2_kernel(int P) {
    __shared__ int sm[128];
    int t = threadIdx.x;
    sm[t] = (t < P) ? g_partials[t] : 0;
    __syncthreads();
    for (int off = 1; off < 128; off <<= 1) {
        int x = (t >= off) ? sm[t - off] : 0;
        __syncthreads();
        if (t >= off) sm[t] += x;
        __syncthreads();
    }
    if (t < P) g_partials[t] = (t > 0) ? sm[t - 1] : 0;
    if (t == P - 1) g_rowptr[Nn] = sm[P - 1];
}

__global__ void scan3_kernel() {
    int i = blockIdx.x * blockDim.x + threadIdx.x;
    if (i < Nn) {
        int v = g_rowptr[i] + g_partials[i / SCAN_CHUNK];
        g_rowptr[i] = v;
        g_cursor[i] = v;
    }
}

// ---------------- permute edges into CSR-by-dst ----------------------------
__global__ void permute_kernel(const int* __restrict__ src, const int* __restrict__ dst) {
    int e = blockIdx.x * blockDim.x + threadIdx.x;
    if (e < Ee) {
        int pos = atomicAdd(&g_cursor[dst[e]], 1);
        g_csrc[pos] = src[e];
    }
}

// ---------------- warp-specialized fused layer (tf32 tensor GEMM) -----------
// 384 threads: warps 0-7 = producers (CSR gather of 32-row A chunks, double
// buffered), warps 8-11 = consumers (3xTF32 mma.sync GEMM + bias + relu).
__global__ __launch_bounds__(384, 2)
void gcn_ws_kernel(const float* __restrict__ h,
                   const float* __restrict__ W,
                   const float* __restrict__ bias,
                   float* __restrict__ out, int M) {
    extern __shared__ float smem[];
    float* Wt = smem;                       // [128][WP] transposed: Wt[n][k]
    float* As = smem + SMEM_W_FLOATS;       // 2 x [32][AP]

    int tid = threadIdx.x;
    int row0 = blockIdx.x * 128;

    if (tid < 256) {
        // ================= producers =================
        int w = tid >> 5;                   // 0..7
        int lane = tid & 31;
#pragma unroll 1
        for (int c0 = 0; c0 < 4; ++c0) {
            int bsel = c0 & 1;
            if (c0 >= 2) bar_sync(BAR_FREE0 + bsel, 384);
            float* Ab = As + bsel * 32 * AP;
#pragma unroll 1
            for (int q = 0; q < 4; ++q) {
                int row_local = w + 8 * q;              // 0..31
                int node = row0 + c0 * 32 + row_local;
                float4 acc = make_float4(0.f, 0.f, 0.f, 0.f);
                if (node < M) {
                    int e = __ldg(&g_rowptr[node]);
                    int end = __ldg(&g_rowptr[node + 1]);
                    for (; e + 1 < end; e += 2) {
                        int s0 = __ldg(&g_csrc[e]);
                        int s1 = __ldg(&g_csrc[e + 1]);
                        float n0 = __ldg(&g_norm_out[s0]);
                        float n1 = __ldg(&g_norm_out[s1]);
                        float4 v0 = *((const float4*)(h + (size_t)s0 * Hh) + lane);
                        float4 v1 = *((const float4*)(h + (size_t)s1 * Hh) + lane);
                        acc.x += v0.x * n0 + v1.x * n1;
                        acc.y += v0.y * n0 + v1.y * n1;
                        acc.z += v0.z * n0 + v1.z * n1;
                        acc.w += v0.w * n0 + v1.w * n1;
                    }
                    if (e < end) {
                        int s0 = __ldg(&g_csrc[e]);
                        float n0 = __ldg(&g_norm_out[s0]);
                        float4 v0 = *((const float4*)(h + (size_t)s0 * Hh) + lane);
                        acc.x += v0.x * n0;
                        acc.y += v0.y * n0;
                        acc.z += v0.z * n0;
                        acc.w += v0.w * n0;
                    }
                    float ni = __ldg(&g_norm_in[node]);
                    acc.x *= ni; acc.y *= ni; acc.z *= ni; acc.w *= ni;
                }
                float* d = Ab + row_local * AP + lane * 4;
                d[0] = acc.x; d[1] = acc.y; d[2] = acc.z; d[3] = acc.w;
            }
            bar_arrive(BAR_FULL0 + bsel, 384);
        }
    } else {
        // ================= consumers =================
        int ctid = tid - 256;               // 0..127
        int cw = ctid >> 5;                 // warp 0..3 -> n0 = cw*32
        int lane = ctid & 31;
        int n0 = cw * 32;
        int grp = lane >> 2;                // 0..7
        int qr  = lane & 3;                 // 0..3

        // stage W transposed: Wt[n][k] = W[k][n]  (coalesced reads)
        for (int i = ctid; i < 128 * 128; i += 128) {
            int k = i >> 7, n = i & 127;
            Wt[n * WP + k] = W[i];
        }

        // bias fragments: col = n0 + nt*8 + 2*qr
        float2 bv[4];
#pragma unroll
        for (int nt = 0; nt < 4; ++nt)
            bv[nt] = *(const float2*)(bias + n0 + nt * 8 + 2 * qr);

        bar_sync(BAR_CONS, 128);

#pragma unroll 1
        for (int c0 = 0; c0 < 4; ++c0) {
            int bsel = c0 & 1;
            bar_sync(BAR_FULL0 + bsel, 384);
            const float* Ab = As + bsel * 32 * AP;

            float acc[2][4][4];
#pragma unroll
            for (int mt = 0; mt < 2; mt++)
#pragma unroll
                for (int nt = 0; nt < 4; nt++)
#pragma unroll
                    for (int j = 0; j < 4; j++) acc[mt][nt][j] = 0.f;

#pragma unroll 1
            for (int ks = 0; ks < 16; ++ks) {
                int k0 = ks * 8;
                // A fragments for 2 m16 tiles (rows mt*16 + grp {,+8})
                unsigned ah[2][4], al[2][4];
#pragma unroll
                for (int mt = 0; mt < 2; mt++) {
                    float a0 = Ab[(mt * 16 + grp) * AP + k0 + qr];
                    float a1 = Ab[(mt * 16 + grp + 8) * AP + k0 + qr];
                    float a2 = Ab[(mt * 16 + grp) * AP + k0 + qr + 4];
                    float a3 = Ab[(mt * 16 + grp + 8) * AP + k0 + qr + 4];
                    tf32_split(a0, ah[mt][0], al[mt][0]);
                    tf32_split(a1, ah[mt][1], al[mt][1]);
                    tf32_split(a2, ah[mt][2], al[mt][2]);
                    tf32_split(a3, ah[mt][3], al[mt][3]);
                }
#pragma unroll
                for (int nt = 0; nt < 4; ++nt) {
                    int n = n0 + nt * 8 + grp;
                    float b0 = Wt[n * WP + k0 + qr];
                    float b1 = Wt[n * WP + k0 + qr + 4];
                    unsigned bh0, bl0, bh1, bl1;
                    tf32_split(b0, bh0, bl0);
                    tf32_split(b1, bh1, bl1);
#pragma unroll
                    for (int mt = 0; mt < 2; mt++) {
                        mma_tf32(acc[mt][nt], ah[mt], bh0, bh1);  // hi*hi
                        mma_tf32(acc[mt][nt], al[mt], bh0, bh1);  // lo*hi
                        mma_tf32(acc[mt][nt], ah[mt], bl0, bl1);  // hi*lo
                    }
                }
            }

            if (c0 < 2) bar_arrive(BAR_FREE0 + bsel, 384);

            // epilogue: bias + relu + store
            // c0,c1 -> (row = mt*16+grp, col = nt*8+2*qr {,+1})
            // c2,c3 -> row +8
#pragma unroll
            for (int mt = 0; mt < 2; mt++) {
#pragma unroll
                for (int nt = 0; nt < 4; nt++) {
                    int col = n0 + nt * 8 + 2 * qr;
                    int gr0 = row0 + c0 * 32 + mt * 16 + grp;
                    if (gr0 < M) {
                        float2 o;
                        o.x = fmaxf(acc[mt][nt][0] + bv[nt].x, 0.f);
                        o.y = fmaxf(acc[mt][nt][1] + bv[nt].y, 0.f);
                        *(float2*)(out + (size_t)gr0 * 128 + col) = o;
                    }
                    int gr1 = gr0 + 8;
                    if (gr1 < M) {
                        float2 o;
                        o.x = fmaxf(acc[mt][nt][2] + bv[nt].x, 0.f);
                        o.y = fmaxf(acc[mt][nt][3] + bv[nt].y, 0.f);
                        *(float2*)(out + (size_t)gr1 * 128 + col) = o;
                    }
                }
            }
        }
    }
}

// ---------------- readout: g[node2graph[n]] += h[n] ------------------------
__global__ void readout_kernel(const float* __restrict__ h,
                               const int* __restrict__ n2g) {
    int warp = (blockIdx.x * blockDim.x + threadIdx.x) >> 5;
    int lane = threadIdx.x & 31;
    if (warp >= Nn) return;
    int g = n2g[warp];
    float4 v = *((const float4*)(h + (size_t)warp * Hh) + lane);
    atomicAdd((float4*)(g_gsum + (size_t)g * Hh) + lane, v);
}

// ---------------- MLP head: relu(g@Wm1+bm1) @ Wm2 + bm2 --------------------
__global__ void mlp_kernel(const float* __restrict__ Wm1, const float* __restrict__ bm1,
                           const float* __restrict__ Wm2, const float* __restrict__ bm2,
                           float* __restrict__ out) {
    int gid = blockIdx.x;        // 0..G-1
    int j = threadIdx.x;         // 0..127
    const float* grow = g_gsum + (size_t)gid * Hh;
    float acc = bm1[j];
#pragma unroll 8
    for (int k = 0; k < Hh; k++) acc += grow[k] * Wm1[(size_t)k * Hh + j];
    acc = fmaxf(acc, 0.f);

    __shared__ float sm[Hh];
    sm[j] = acc * Wm2[j];        // Wm2 is [H,1]
    __syncthreads();
    for (int s = 64; s > 0; s >>= 1) {
        if (j < s) sm[j] += sm[j + s];
        __syncthreads();
    }
    if (j == 0) out[gid] = sm[0] + bm2[0];
}

// ---------------- launch ----------------------------------------------------
extern "C" void kernel_launch(void* const* d_in, const int* in_sizes, int n_in,
                              void* d_out, int out_size) {
    const float* x   = (const float*)d_in[0];
    const int* src   = (const int*)d_in[1];
    const int* dst   = (const int*)d_in[2];
    const int* n2g   = (const int*)d_in[3];
    const float* W0  = (const float*)d_in[4];
    const float* b0  = (const float*)d_in[5];
    const float* W1  = (const float*)d_in[6];
    const float* b1  = (const float*)d_in[7];
    const float* W2  = (const float*)d_in[8];
    const float* b2  = (const float*)d_in[9];
    const float* Wm1 = (const float*)d_in[10];
    const float* bm1 = (const float*)d_in[11];
    const float* Wm2 = (const float*)d_in[12];
    const float* bm2 = (const float*)d_in[13];
    float* out = (float*)d_out;

    void *p_h0, *p_h1;
    cudaGetSymbolAddress(&p_h0, g_h0);
    cudaGetSymbolAddress(&p_h1, g_h1);
    float* h0  = (float*)p_h0;
    float* h1  = (float*)p_h1;

    static int smem_set = 0;
    if (!smem_set) {
        cudaFuncSetAttribute(gcn_ws_kernel,
                             cudaFuncAttributeMaxDynamicSharedMemorySize,
                             FUSED_SMEM);
        smem_set = 1;
    }

    const int LAYER_BLOCKS = (Nn + 127) / 128;   // 782
    const int RD_BLOCKS    = (Nn + 7) / 8;

    // ---- CSR build + norms (once per launch) ----
    zero_cnt_kernel<<<(Nn + 255) / 256, 256>>>();
    hist_kernel<<<(Ee + 255) / 256, 256>>>(src, dst);
    norm_kernel<<<(Nn + 255) / 256, 256>>>();
    scan1_kernel<<<NBLK_SCAN, 256>>>();
    scan2_kernel<<<1, 128>>>(NBLK_SCAN);
    scan3_kernel<<<(Nn + 255) / 256, 256>>>();
    permute_kernel<<<(Ee + 255) / 256, 256>>>(src, dst);

    // ---- 3 warp-specialized fused GCN layers ----
    gcn_ws_kernel<<<LAYER_BLOCKS, 384, FUSED_SMEM>>>(x,  W0, b0, h0, Nn);
    gcn_ws_kernel<<<LAYER_BLOCKS, 384, FUSED_SMEM>>>(h0, W1, b1, h1, Nn);
    gcn_ws_kernel<<<LAYER_BLOCKS, 384, FUSED_SMEM>>>(h1, W2, b2, h0, Nn);

    // ---- readout + MLP head ----
    zero_g_kernel<<<(Gg * Hh + 255) / 256, 256>>>();
    readout_kernel<<<RD_BLOCKS, 256>>>(h0, n2g);
    mlp_kernel<<<Gg, Hh>>>(Wm1, bm1, Wm2, bm2, out);
}

// round 16
// speedup vs baseline: 1.1941x; 1.1941x over previous
#include <cuda_runtime.h>
#include <cuda_bf16.h>
#include <math.h>

#define Nn 100000
#define Ee 1600000
#define Gg 512
#define Hh 128
#define SCAN_CHUNK 1024
#define NBLK_SCAN ((Nn + SCAN_CHUNK - 1) / SCAN_CHUNK)   // 98

#define AP2 130                                 // A-chunk row pitch (uint2)
#define WP2 130                                 // Wt row pitch (uint2)
#define SMEM_W_U2 (128 * WP2)                   // W transposed, split hi/lo
#define SMEM_A_U2 (2 * 32 * AP2)                // double-buffered 32-row chunks
#define FUSED_SMEM ((SMEM_W_U2 + SMEM_A_U2) * 8)   // 199680 bytes

#define NTHREADS 768                             // 16 producer + 8 consumer warps

#define BAR_FULL0 1
#define BAR_FULL1 2
#define BAR_FREE0 3
#define BAR_FREE1 4
#define BAR_CONS  5

__device__ __forceinline__ void bar_sync(int id, int cnt) {
    asm volatile("bar.sync %0, %1;" :: "r"(id), "r"(cnt) : "memory");
}
__device__ __forceinline__ void bar_arrive(int id, int cnt) {
    asm volatile("bar.arrive %0, %1;" :: "r"(id), "r"(cnt) : "memory");
}

// fp32 -> (tf32 hi, tf32 lo) split
__device__ __forceinline__ uint2 tf32_split(float a) {
    unsigned hi, lo;
    asm("cvt.rna.tf32.f32 %0, %1;" : "=r"(hi) : "f"(a));
    float r = a - __uint_as_float(hi);
    asm("cvt.rna.tf32.f32 %0, %1;" : "=r"(lo) : "f"(r));
    return make_uint2(hi, lo);
}

__device__ __forceinline__ void mma_tf32(float* c, const unsigned* a,
                                         unsigned b0, unsigned b1) {
    asm volatile(
        "mma.sync.aligned.m16n8k8.row.col.f32.tf32.tf32.f32 "
        "{%0,%1,%2,%3}, {%4,%5,%6,%7}, {%8,%9}, {%0,%1,%2,%3};"
        : "+f"(c[0]), "+f"(c[1]), "+f"(c[2]), "+f"(c[3])
        : "r"(a[0]), "r"(a[1]), "r"(a[2]), "r"(a[3]), "r"(b0), "r"(b1));
}

// ---------------- scratch (device globals; no allocation allowed) ----------
__device__ float g_h0[(size_t)Nn * Hh];
__device__ float g_h1[(size_t)Nn * Hh];
__device__ float g_norm_out[Nn];
__device__ float g_norm_in[Nn];
__device__ float g_gsum[(size_t)Gg * Hh];

__device__ int g_cnt_in[Nn];
__device__ int g_cnt_out[Nn];
__device__ int g_rowptr[Nn + 1];
__device__ int g_cursor[Nn];
__device__ int g_csrc[Ee];
__device__ int g_partials[256];

// ---------------- zero kernels ---------------------------------------------
__global__ void zero_cnt_kernel() {
    int i = blockIdx.x * blockDim.x + threadIdx.x;
    if (i < Nn) { g_cnt_in[i] = 0; g_cnt_out[i] = 0; }
}

__global__ void zero_g_kernel() {
    int i = blockIdx.x * blockDim.x + threadIdx.x;
    if (i < Gg * Hh) g_gsum[i] = 0.f;
}

// ---------------- histogram (also yields degrees) --------------------------
__global__ void hist_kernel(const int* __restrict__ src, const int* __restrict__ dst) {
    int e = blockIdx.x * blockDim.x + threadIdx.x;
    if (e < Ee) {
        atomicAdd(&g_cnt_in[dst[e]], 1);
        atomicAdd(&g_cnt_out[src[e]], 1);
    }
}

__global__ void norm_kernel() {
    int i = blockIdx.x * blockDim.x + threadIdx.x;
    if (i < Nn) {
        g_norm_out[i] = rsqrtf(fmaxf((float)g_cnt_out[i], 1.f));
        g_norm_in[i]  = rsqrtf(fmaxf((float)g_cnt_in[i], 1.f));
    }
}

// ---------------- 3-phase exclusive scan of g_cnt_in -> g_rowptr -----------
__global__ void scan1_kernel() {
    __shared__ int sm[256];
    int b = blockIdx.x, t = threadIdx.x;
    int base = b * SCAN_CHUNK + t * 4;
    int v[4]; int s = 0;
#pragma unroll
    for (int i = 0; i < 4; i++) {
        int idx = base + i;
        v[i] = (idx < Nn) ? g_cnt_in[idx] : 0;
        s += v[i];
    }
    sm[t] = s;
    __syncthreads();
    for (int off = 1; off < 256; off <<= 1) {
        int x = (t >= off) ? sm[t - off] : 0;
        __syncthreads();
        if (t >= off) sm[t] += x;
        __syncthreads();
    }
    int run = (t > 0) ? sm[t - 1] : 0;
#pragma unroll
    for (int i = 0; i < 4; i++) {
        int idx = base + i;
        if (idx < Nn) g_rowptr[idx] = run;
        run += v[i];
    }
    if (t == 255) g_partials[b] = sm[255];
}

__global__ void scan2_kernel(int P) {
    __shared__ int sm[128];
    int t = threadIdx.x;
    sm[t] = (t < P) ? g_partials[t] : 0;
    __syncthreads();
    for (int off = 1; off < 128; off <<= 1) {
        int x = (t >= off) ? sm[t - off] : 0;
        __syncthreads();
        if (t >= off) sm[t] += x;
        __syncthreads();
    }
    if (t < P) g_partials[t] = (t > 0) ? sm[t - 1] : 0;
    if (t == P - 1) g_rowptr[Nn] = sm[P - 1];
}

__global__ void scan3_kernel() {
    int i = blockIdx.x * blockDim.x + threadIdx.x;
    if (i < Nn) {
        int v = g_rowptr[i] + g_partials[i / SCAN_CHUNK];
        g_rowptr[i] = v;
        g_cursor[i] = v;
    }
}

// ---------------- permute edges into CSR-by-dst ----------------------------
__global__ void permute_kernel(const int* __restrict__ src, const int* __restrict__ dst) {
    int e = blockIdx.x * blockDim.x + threadIdx.x;
    if (e < Ee) {
        int pos = atomicAdd(&g_cursor[dst[e]], 1);
        g_csrc[pos] = src[e];
    }
}

// ---------------- warp-specialized fused layer (tf32, precomputed splits) ---
// 768 threads, 1 CTA/SM: warps 0-15 = producers (CSR gather, write A as
// tf32 hi/lo pairs), warps 16-23 = consumers (pure LDS.64 + HMMA mainloop).
__global__ __launch_bounds__(NTHREADS, 1)
void gcn_ws_kernel(const float* __restrict__ h,
                   const float* __restrict__ W,
                   const float* __restrict__ bias,
                   float* __restrict__ out, int M) {
    extern __shared__ uint2 smem_u2[];
    uint2* Wt = smem_u2;                    // [128][WP2]: Wt[n][k] = split(W[k][n])
    uint2* As = smem_u2 + SMEM_W_U2;        // 2 x [32][AP2]

    int tid = threadIdx.x;
    int row0 = blockIdx.x * 128;

    if (tid < 512) {
        // ================= producers (16 warps) =================
        int w = tid >> 5;                   // 0..15
        int lane = tid & 31;
#pragma unroll 1
        for (int c0 = 0; c0 < 4; ++c0) {
            int bsel = c0 & 1;
            if (c0 >= 2) bar_sync(BAR_FREE0 + bsel, NTHREADS);
            uint2* Ab = As + bsel * 32 * AP2;
#pragma unroll 1
            for (int q = 0; q < 2; ++q) {
                int row_local = w + 16 * q;             // 0..31
                int node = row0 + c0 * 32 + row_local;
                float4 acc = make_float4(0.f, 0.f, 0.f, 0.f);
                if (node < M) {
                    int e = __ldg(&g_rowptr[node]);
                    int end = __ldg(&g_rowptr[node + 1]);
                    for (; e + 1 < end; e += 2) {
                        int s0 = __ldg(&g_csrc[e]);
                        int s1 = __ldg(&g_csrc[e + 1]);
                        float n0 = __ldg(&g_norm_out[s0]);
                        float n1 = __ldg(&g_norm_out[s1]);
                        float4 v0 = *((const float4*)(h + (size_t)s0 * Hh) + lane);
                        float4 v1 = *((const float4*)(h + (size_t)s1 * Hh) + lane);
                        acc.x += v0.x * n0 + v1.x * n1;
                        acc.y += v0.y * n0 + v1.y * n1;
                        acc.z += v0.z * n0 + v1.z * n1;
                        acc.w += v0.w * n0 + v1.w * n1;
                    }
                    if (e < end) {
                        int s0 = __ldg(&g_csrc[e]);
                        float n0 = __ldg(&g_norm_out[s0]);
                        float4 v0 = *((const float4*)(h + (size_t)s0 * Hh) + lane);
                        acc.x += v0.x * n0;
                        acc.y += v0.y * n0;
                        acc.z += v0.z * n0;
                        acc.w += v0.w * n0;
                    }
                    float ni = __ldg(&g_norm_in[node]);
                    acc.x *= ni; acc.y *= ni; acc.z *= ni; acc.w *= ni;
                }
                uint2* d = Ab + row_local * AP2 + lane * 4;
                d[0] = tf32_split(acc.x);
                d[1] = tf32_split(acc.y);
                d[2] = tf32_split(acc.z);
                d[3] = tf32_split(acc.w);
            }
            bar_arrive(BAR_FULL0 + bsel, NTHREADS);
        }
    } else {
        // ================= consumers (8 warps) =================
        int ctid = tid - 512;               // 0..255
        int cw = ctid >> 5;                 // warp 0..7 -> n0 = cw*16
        int lane = ctid & 31;
        int n0 = cw * 16;
        int grp = lane >> 2;                // 0..7
        int qr  = lane & 3;                 // 0..3

        // stage W transposed + split (one time): Wt[n][k] = split(W[k][n])
        for (int i = ctid; i < 128 * 128; i += 256) {
            int k = i >> 7, n = i & 127;
            Wt[n * WP2 + k] = tf32_split(W[i]);
        }

        // bias fragments: col = n0 + nt*8 + 2*qr
        float2 bv[2];
#pragma unroll
        for (int nt = 0; nt < 2; ++nt)
            bv[nt] = *(const float2*)(bias + n0 + nt * 8 + 2 * qr);

        bar_sync(BAR_CONS, 256);

#pragma unroll 1
        for (int c0 = 0; c0 < 4; ++c0) {
            int bsel = c0 & 1;
            bar_sync(BAR_FULL0 + bsel, NTHREADS);
            const uint2* Ab = As + bsel * 32 * AP2;

            float acc[2][2][4];
#pragma unroll
            for (int mt = 0; mt < 2; mt++)
#pragma unroll
                for (int nt = 0; nt < 2; nt++)
#pragma unroll
                    for (int j = 0; j < 4; j++) acc[mt][nt][j] = 0.f;

#pragma unroll 2
            for (int ks = 0; ks < 16; ++ks) {
                int k0 = ks * 8;
                // A fragments for 2 m16 tiles (rows mt*16 + grp {,+8})
                unsigned ah[2][4], al[2][4];
#pragma unroll
                for (int mt = 0; mt < 2; mt++) {
                    uint2 p0 = Ab[(mt * 16 + grp) * AP2 + k0 + qr];
                    uint2 p1 = Ab[(mt * 16 + grp + 8) * AP2 + k0 + qr];
                    uint2 p2 = Ab[(mt * 16 + grp) * AP2 + k0 + qr + 4];
                    uint2 p3 = Ab[(mt * 16 + grp + 8) * AP2 + k0 + qr + 4];
                    ah[mt][0] = p0.x; al[mt][0] = p0.y;
                    ah[mt][1] = p1.x; al[mt][1] = p1.y;
                    ah[mt][2] = p2.x; al[mt][2] = p2.y;
                    ah[mt][3] = p3.x; al[mt][3] = p3.y;
                }
#pragma unroll
                for (int nt = 0; nt < 2; ++nt) {
                    int n = n0 + nt * 8 + grp;
                    uint2 q0 = Wt[n * WP2 + k0 + qr];
                    uint2 q1 = Wt[n * WP2 + k0 + qr + 4];
#pragma unroll
                    for (int mt = 0; mt < 2; mt++) {
                        mma_tf32(acc[mt][nt], ah[mt], q0.x, q1.x);  // hi*hi
                        mma_tf32(acc[mt][nt], al[mt], q0.x, q1.x);  // lo*hi
                        mma_tf32(acc[mt][nt], ah[mt], q0.y, q1.y);  // hi*lo
                    }
                }
            }

            if (c0 < 2) bar_arrive(BAR_FREE0 + bsel, NTHREADS);

            // epilogue: bias + relu + store
#pragma unroll
            for (int mt = 0; mt < 2; mt++) {
#pragma unroll
                for (int nt = 0; nt < 2; nt++) {
                    int col = n0 + nt * 8 + 2 * qr;
                    int gr0 = row0 + c0 * 32 + mt * 16 + grp;
                    if (gr0 < M) {
                        float2 o;
                        o.x = fmaxf(acc[mt][nt][0] + bv[nt].x, 0.f);
                        o.y = fmaxf(acc[mt][nt][1] + bv[nt].y, 0.f);
                        *(float2*)(out + (size_t)gr0 * 128 + col) = o;
                    }
                    int gr1 = gr0 + 8;
                    if (gr1 < M) {
                        float2 o;
                        o.x = fmaxf(acc[mt][nt][2] + bv[nt].x, 0.f);
                        o.y = fmaxf(acc[mt][nt][3] + bv[nt].y, 0.f);
                        *(float2*)(out + (size_t)gr1 * 128 + col) = o;
                    }
                }
            }
        }
    }
}

// ---------------- readout: g[node2graph[n]] += h[n] ------------------------
__global__ void readout_kernel(const float* __restrict__ h,
                               const int* __restrict__ n2g) {
    int warp = (blockIdx.x * blockDim.x + threadIdx.x) >> 5;
    int lane = threadIdx.x & 31;
    if (warp >= Nn) return;
    int g = n2g[warp];
    float4 v = *((const float4*)(h + (size_t)warp * Hh) + lane);
    atomicAdd((float4*)(g_gsum + (size_t)g * Hh) + lane, v);
}

// ---------------- MLP head: relu(g@Wm1+bm1) @ Wm2 + bm2 --------------------
__global__ void mlp_kernel(const float* __restrict__ Wm1, const float* __restrict__ bm1,
                           const float* __restrict__ Wm2, const float* __restrict__ bm2,
                           float* __restrict__ out) {
    int gid = blockIdx.x;        // 0..G-1
    int j = threadIdx.x;         // 0..127
    const float* grow = g_gsum + (size_t)gid * Hh;
    float acc = bm1[j];
#pragma unroll 8
    for (int k = 0; k < Hh; k++) acc += grow[k] * Wm1[(size_t)k * Hh + j];
    acc = fmaxf(acc, 0.f);

    __shared__ float sm[Hh];
    sm[j] = acc * Wm2[j];        // Wm2 is [H,1]
    __syncthreads();
    for (int s = 64; s > 0; s >>= 1) {
        if (j < s) sm[j] += sm[j + s];
        __syncthreads();
    }
    if (j == 0) out[gid] = sm[0] + bm2[0];
}

// ---------------- launch ----------------------------------------------------
extern "C" void kernel_launch(void* const* d_in, const int* in_sizes, int n_in,
                              void* d_out, int out_size) {
    const float* x   = (const float*)d_in[0];
    const int* src   = (const int*)d_in[1];
    const int* dst   = (const int*)d_in[2];
    const int* n2g   = (const int*)d_in[3];
    const float* W0  = (const float*)d_in[4];
    const float* b0  = (const float*)d_in[5];
    const float* W1  = (const float*)d_in[6];
    const float* b1  = (const float*)d_in[7];
    const float* W2  = (const float*)d_in[8];
    const float* b2  = (const float*)d_in[9];
    const float* Wm1 = (const float*)d_in[10];
    const float* bm1 = (const float*)d_in[11];
    const float* Wm2 = (const float*)d_in[12];
    const float* bm2 = (const float*)d_in[13];
    float* out = (float*)d_out;

    void *p_h0, *p_h1;
    cudaGetSymbolAddress(&p_h0, g_h0);
    cudaGetSymbolAddress(&p_h1, g_h1);
    float* h0  = (float*)p_h0;
    float* h1  = (float*)p_h1;

    static int smem_set = 0;
    if (!smem_set) {
        cudaFuncSetAttribute(gcn_ws_kernel,
                             cudaFuncAttributeMaxDynamicSharedMemorySize,
                             FUSED_SMEM);
        smem_set = 1;
    }

    const int LAYER_BLOCKS = (Nn + 127) / 128;   // 782
    const int RD_BLOCKS    = (Nn + 7) / 8;

    // ---- CSR build + norms (once per launch) ----
    zero_cnt_kernel<<<(Nn + 255) / 256, 256>>>();
    hist_kernel<<<(Ee + 255) / 256, 256>>>(src, dst);
    norm_kernel<<<(Nn + 255) / 256, 256>>>();
    scan1_kernel<<<NBLK_SCAN, 256>>>();
    scan2_kernel<<<1, 128>>>(NBLK_SCAN);
    scan3_kernel<<<(Nn + 255) / 256, 256>>>();
    permute_kernel<<<(Ee + 255) / 256, 256>>>(src, dst);

    // ---- 3 warp-specialized fused GCN layers ----
    gcn_ws_kernel<<<LAYER_BLOCKS, NTHREADS, FUSED_SMEM>>>(x,  W0, b0, h0, Nn);
    gcn_ws_kernel<<<LAYER_BLOCKS, NTHREADS, FUSED_SMEM>>>(h0, W1, b1, h1, Nn);
    gcn_ws_kernel<<<LAYER_BLOCKS, NTHREADS, FUSED_SMEM>>>(h1, W2, b2, h0, Nn);

    // ---- readout + MLP head ----
    zero_g_kernel<<<(Gg * Hh + 255) / 256, 256>>>();
    readout_kernel<<<RD_BLOCKS, 256>>>(h0, n2g);
    mlp_kernel<<<Gg, Hh>>>(Wm1, bm1, Wm2, bm2, out);
}